// round 1
// baseline (speedup 1.0000x reference)
#include <cuda_runtime.h>
#include <cstdint>
#include <cstddef>

// Problem constants (fixed shapes per reference)
#define NV 100000
#define NE 300000
#define DD 128
#define NL 3
#define EPS_BN 1e-5f

// GEMM tiling
#define BM 64
#define BN 256
#define GEMM_THREADS 256
#define GEMM_BLOCKS ((NV + BM - 1) / BM)          // 1563
#define GEMM_SMEM ((BM * DD + DD * BN) * 4)       // 163840 bytes

// Aggregation tiling
#define AGG_WARPS 16
#define AGG_NPW 8
#define AGG_NODES (AGG_WARPS * AGG_NPW)           // 128 nodes / block
#define AGG_BLOCKS ((NV + AGG_NODES - 1) / AGG_NODES)  // 782

// ---------------- scratch (static device globals; no allocs allowed) -------
__device__ float g_h0[(size_t)NV * DD];   // h0 -> agg -> g (in place)
__device__ float g_h1[(size_t)NV * DD];   // h1
__device__ float g_xb[(size_t)NV * DD];   // layer activations (ping)
__device__ int   g_deg[NV];
__device__ int   g_rowptr[NV + 1];
__device__ int   g_cursor[NV];
__device__ int   g_adj[2 * NE];
__device__ float g_dinv[NV];
__device__ float g_part[(size_t)AGG_BLOCKS * 256];
__device__ float g_part2[8 * 256];
__device__ float g_stats[256];            // [0:128) mu, [128:256) rsigma

// ---------------- packed f32x2 helpers (FFMA2) -----------------------------
typedef unsigned long long u64;

__device__ __forceinline__ u64 pack_dup(float x) {
    unsigned u = __float_as_uint(x);
    u64 r;
    asm("mov.b64 %0, {%1, %1};" : "=l"(r) : "r"(u));
    return r;
}
__device__ __forceinline__ u64 ffma2(u64 a, u64 b, u64 c) {
    u64 d;
    asm("fma.rn.f32x2 %0, %1, %2, %3;" : "=l"(d) : "l"(a), "l"(b), "l"(c));
    return d;
}
__device__ __forceinline__ float2 unpack2(u64 a) {
    unsigned lo, hi;
    asm("mov.b64 {%0, %1}, %2;" : "=r"(lo), "=r"(hi) : "l"(a));
    return make_float2(__uint_as_float(lo), __uint_as_float(hi));
}

// ---------------- CSR build -------------------------------------------------
__global__ void zero_deg_kernel() {
    int i = blockIdx.x * 256 + threadIdx.x;
    if (i < NV) g_deg[i] = 0;
}

__global__ void deg_kernel(const int2* __restrict__ edges) {
    int e = blockIdx.x * 256 + threadIdx.x;
    if (e >= NE) return;
    int2 ed = edges[e];
    atomicAdd(&g_deg[ed.x], 1);
    atomicAdd(&g_deg[ed.y], 1);
}

__global__ void scan_kernel() {
    __shared__ int sh[1024];
    int t = threadIdx.x;
    const int CH = (NV + 1023) / 1024;   // 98
    int base = t * CH;
    int s = 0;
    for (int i = 0; i < CH; i++) {
        int v = base + i;
        if (v < NV) s += g_deg[v];
    }
    sh[t] = s;
    __syncthreads();
    // inclusive Hillis-Steele scan
    for (int off = 1; off < 1024; off <<= 1) {
        int val = sh[t];
        int add = (t >= off) ? sh[t - off] : 0;
        __syncthreads();
        sh[t] = val + add;
        __syncthreads();
    }
    int run = (t == 0) ? 0 : sh[t - 1];
    for (int i = 0; i < CH; i++) {
        int v = base + i;
        if (v >= NV) break;
        g_rowptr[v] = run;
        g_cursor[v] = run;
        int d = g_deg[v];
        g_dinv[v] = 1.0f / (1.0f + (float)d);
        run += d;
    }
    if (t == 1023) g_rowptr[NV] = run;
}

__global__ void fill_kernel(const int2* __restrict__ edges) {
    int e = blockIdx.x * 256 + threadIdx.x;
    if (e >= NE) return;
    int2 ed = edges[e];
    int p = atomicAdd(&g_cursor[ed.x], 1);
    g_adj[p] = ed.y;
    int q = atomicAdd(&g_cursor[ed.y], 1);
    g_adj[q] = ed.x;
}

// ---------------- fused dual GEMM: [h0|h1] = X @ [W0^T|W1^T] + [b0|b1] -----
// block: BM=64 rows x BN=256 cols (both matrices), 256 threads, 8x8 per thread
__global__ void __launch_bounds__(GEMM_THREADS, 1)
gemm_kernel(const float* __restrict__ Xext, int use_ext,
            const float* __restrict__ W0, const float* __restrict__ b0,
            const float* __restrict__ W1, const float* __restrict__ b1)
{
    const float* X = use_ext ? Xext : g_xb;
    extern __shared__ float smem[];
    float* Xs = smem;            // [BM][DD]
    float* Ws = smem + BM * DD;  // [DD][BN]  Ws[k][j] = Wc[j][k]

    int tid  = threadIdx.x;
    int row0 = blockIdx.x * BM;

    // Load X tile [64][128], coalesced, zero-pad OOB rows
    #pragma unroll
    for (int it = 0; it < 8; ++it) {
        int m = it * 8 + (tid >> 5);
        int k = (tid & 31) * 4;
        float4 v = make_float4(0.f, 0.f, 0.f, 0.f);
        int gr = row0 + m;
        if (gr < NV) v = *(const float4*)(X + (size_t)gr * DD + k);
        *(float4*)(Xs + m * DD + k) = v;
    }
    // Load W transposed into Ws[k][j]; lanes span j -> conflict-free STS
    #pragma unroll
    for (int it = 0; it < 32; ++it) {
        int k = it * 4;
        int j = tid;
        const float* src = (j < DD) ? (W0 + (size_t)j * DD + k)
                                    : (W1 + (size_t)(j - DD) * DD + k);
        float4 v = *(const float4*)src;
        Ws[(k + 0) * BN + j] = v.x;
        Ws[(k + 1) * BN + j] = v.y;
        Ws[(k + 2) * BN + j] = v.z;
        Ws[(k + 3) * BN + j] = v.w;
    }
    __syncthreads();

    int tc = (tid & 31) * 8;   // col base (0..248)
    int tr = (tid >> 5) * 8;   // row base (0..56)

    u64 acc[8][4];
    #pragma unroll
    for (int r = 0; r < 8; ++r)
        #pragma unroll
        for (int p = 0; p < 4; ++p) acc[r][p] = 0ull;

    #pragma unroll 4
    for (int k = 0; k < DD; ++k) {
        ulonglong2 t0 = *(const ulonglong2*)(Ws + k * BN + tc);
        ulonglong2 t1 = *(const ulonglong2*)(Ws + k * BN + tc + 4);
        u64 bf0 = t0.x, bf1 = t0.y, bf2 = t1.x, bf3 = t1.y;
        #pragma unroll
        for (int r = 0; r < 8; ++r) {
            u64 a2 = pack_dup(Xs[(tr + r) * DD + k]);  // LDS broadcast within warp
            acc[r][0] = ffma2(a2, bf0, acc[r][0]);
            acc[r][1] = ffma2(a2, bf1, acc[r][1]);
            acc[r][2] = ffma2(a2, bf2, acc[r][2]);
            acc[r][3] = ffma2(a2, bf3, acc[r][3]);
        }
    }

    // Epilogue: bias + route to h0/h1
    float bias[8];
    #pragma unroll
    for (int cc = 0; cc < 8; ++cc) {
        int c = tc + cc;
        bias[cc] = (c < DD) ? b0[c] : b1[c - DD];
    }
    float* Hout;
    int cb;
    if (tc < DD) { Hout = g_h0; cb = tc; }
    else         { Hout = g_h1; cb = tc - DD; }

    #pragma unroll
    for (int r = 0; r < 8; ++r) {
        int gr = row0 + tr + r;
        if (gr >= NV) continue;
        float2 u0 = unpack2(acc[r][0]);
        float2 u1 = unpack2(acc[r][1]);
        float2 u2 = unpack2(acc[r][2]);
        float2 u3 = unpack2(acc[r][3]);
        float4 o0 = make_float4(u0.x + bias[0], u0.y + bias[1], u1.x + bias[2], u1.y + bias[3]);
        float4 o1 = make_float4(u2.x + bias[4], u2.y + bias[5], u3.x + bias[6], u3.y + bias[7]);
        *(float4*)(Hout + (size_t)gr * DD + cb)     = o0;
        *(float4*)(Hout + (size_t)gr * DD + cb + 4) = o1;
    }
}

// ---------------- aggregate (CSR gather) + dinv scale + BN partial sums ----
// one warp per 8 nodes; lane covers 4 columns (float4)
__global__ void __launch_bounds__(512)
agg_stats_kernel()
{
    __shared__ float sh[AGG_WARPS * 256];
    int tid  = threadIdx.x;
    int warp = tid >> 5;
    int lane = tid & 31;
    int gw   = blockIdx.x * AGG_WARPS + warp;
    int n0   = gw * AGG_NPW;
    int c4   = lane * 4;

    float4 s = make_float4(0.f, 0.f, 0.f, 0.f);
    float4 q = make_float4(0.f, 0.f, 0.f, 0.f);

    for (int i = 0; i < AGG_NPW; i++) {
        int n = n0 + i;
        if (n >= NV) break;
        float4 acc = *(const float4*)(g_h0 + (size_t)n * DD + c4);
        int beg = g_rowptr[n];
        int end = g_rowptr[n + 1];
        for (int j = beg; j < end; j++) {
            int nb = g_adj[j];
            float4 h = *(const float4*)(g_h1 + (size_t)nb * DD + c4);
            acc.x += h.x; acc.y += h.y; acc.z += h.z; acc.w += h.w;
        }
        float di = g_dinv[n];
        acc.x *= di; acc.y *= di; acc.z *= di; acc.w *= di;
        *(float4*)(g_h0 + (size_t)n * DD + c4) = acc;   // g in place
        s.x += acc.x; s.y += acc.y; s.z += acc.z; s.w += acc.w;
        q.x += acc.x * acc.x; q.y += acc.y * acc.y;
        q.z += acc.z * acc.z; q.w += acc.w * acc.w;
    }

    float* shw = sh + warp * 256;
    shw[c4 + 0] = s.x; shw[c4 + 1] = s.y; shw[c4 + 2] = s.z; shw[c4 + 3] = s.w;
    shw[128 + c4 + 0] = q.x; shw[128 + c4 + 1] = q.y;
    shw[128 + c4 + 2] = q.z; shw[128 + c4 + 3] = q.w;
    __syncthreads();

    if (tid < 256) {
        float tot = 0.f;
        #pragma unroll
        for (int w = 0; w < AGG_WARPS; w++) tot += sh[w * 256 + tid];
        g_part[(size_t)blockIdx.x * 256 + tid] = tot;
    }
}

__global__ void finalizeA_kernel() {
    int b = blockIdx.x, t = threadIdx.x;
    const int CH = (AGG_BLOCKS + 7) / 8;
    int r0 = b * CH;
    int r1 = r0 + CH; if (r1 > AGG_BLOCKS) r1 = AGG_BLOCKS;
    float s = 0.f;
    for (int r = r0; r < r1; r++) s += g_part[(size_t)r * 256 + t];
    g_part2[b * 256 + t] = s;
}

__global__ void finalizeB_kernel() {
    __shared__ float sh[256];
    int t = threadIdx.x;
    float s = 0.f;
    #pragma unroll
    for (int b = 0; b < 8; b++) s += g_part2[b * 256 + t];
    sh[t] = s;
    __syncthreads();
    if (t < 128) {
        float inv = 1.0f / (float)NV;
        float mu  = sh[t] * inv;
        float var = sh[t + 128] * inv - mu * mu;
        g_stats[t]       = mu;
        g_stats[t + 128] = rsqrtf(var + EPS_BN);
    }
}

// ---------------- BN apply + ReLU (+ residual) ------------------------------
__global__ void __launch_bounds__(256)
bnrelu_kernel(const float* __restrict__ gamma, const float* __restrict__ beta,
              const float* __restrict__ res, float* __restrict__ outExt, int use_ext)
{
    float* out = use_ext ? outExt : g_xb;
    int idx = blockIdx.x * 256 + threadIdx.x;  // float4 index
    if (idx >= NV * 32) return;
    int c = (idx & 31) * 4;

    float4 g = *(const float4*)(g_h0 + (size_t)idx * 4);
    float mu0 = g_stats[c + 0], mu1 = g_stats[c + 1], mu2 = g_stats[c + 2], mu3 = g_stats[c + 3];
    float rs0 = g_stats[128 + c + 0], rs1 = g_stats[128 + c + 1];
    float rs2 = g_stats[128 + c + 2], rs3 = g_stats[128 + c + 3];
    float ga0 = gamma[c + 0], ga1 = gamma[c + 1], ga2 = gamma[c + 2], ga3 = gamma[c + 3];
    float be0 = beta[c + 0], be1 = beta[c + 1], be2 = beta[c + 2], be3 = beta[c + 3];

    float v0 = ga0 * (g.x - mu0) * rs0 + be0;
    float v1 = ga1 * (g.y - mu1) * rs1 + be1;
    float v2 = ga2 * (g.z - mu2) * rs2 + be2;
    float v3 = ga3 * (g.w - mu3) * rs3 + be3;

    if (res != nullptr) {
        float4 r4 = *(const float4*)(res + (size_t)idx * 4);
        v0 += r4.x; v1 += r4.y; v2 += r4.z; v3 += r4.w;
    }
    float4 o = make_float4(fmaxf(v0, 0.f), fmaxf(v1, 0.f), fmaxf(v2, 0.f), fmaxf(v3, 0.f));
    *(float4*)(out + (size_t)idx * 4) = o;
}

// ---------------- launch ----------------------------------------------------
extern "C" void kernel_launch(void* const* d_in, const int* in_sizes, int n_in,
                              void* d_out, int out_size)
{
    const float* features = (const float*)d_in[0];
    const int2*  edges    = (const int2*)d_in[1];
    const float* W0       = (const float*)d_in[2];
    const float* b0       = (const float*)d_in[3];
    const float* W1       = (const float*)d_in[4];
    const float* b1       = (const float*)d_in[5];
    const float* gamma    = (const float*)d_in[6];
    const float* beta     = (const float*)d_in[7];
    float* out = (float*)d_out;

    cudaFuncSetAttribute(gemm_kernel, cudaFuncAttributeMaxDynamicSharedMemorySize, GEMM_SMEM);

    // CSR + degree normalization (rebuilt every call; deterministic work)
    zero_deg_kernel<<<(NV + 255) / 256, 256>>>();
    deg_kernel<<<(NE + 255) / 256, 256>>>(edges);
    scan_kernel<<<1, 1024>>>();
    fill_kernel<<<(NE + 255) / 256, 256>>>(edges);

    for (int l = 0; l < NL; l++) {
        gemm_kernel<<<GEMM_BLOCKS, GEMM_THREADS, GEMM_SMEM>>>(
            features, (l == 0) ? 1 : 0,
            W0 + (size_t)l * DD * DD, b0 + (size_t)l * DD,
            W1 + (size_t)l * DD * DD, b1 + (size_t)l * DD);

        agg_stats_kernel<<<AGG_BLOCKS, 512>>>();
        finalizeA_kernel<<<8, 256>>>();
        finalizeB_kernel<<<1, 256>>>();

        bnrelu_kernel<<<(NV * 32 + 255) / 256, 256>>>(
            gamma + (size_t)l * DD, beta + (size_t)l * DD,
            (l == 2) ? features : nullptr,
            out, (l == 2) ? 1 : 0);
    }
}

// round 6
// speedup vs baseline: 1.4132x; 1.4132x over previous
#include <cuda_runtime.h>
#include <cuda_bf16.h>
#include <cstdint>
#include <cstddef>

// Problem constants (fixed shapes per reference)
#define NV 100000
#define NE 300000
#define DD 128
#define NL 3
#define EPS_BN 1e-5f

// GEMM tiling (mma.sync bf16, 3-term split)
#define TM 128
#define TN 256
#define NTILES ((NV + TM - 1) / TM)  // 782
#define GT 512                        // threads per GEMM block (16 warps)

// smem byte offsets; rows are 128 bf16 = 256B data + 16B pad = 272B pitch
// (272 mod 128 = 16 -> 8 consecutive rows sweep all banks; LDSM conflict-free)
#define PITCH 272
#define OFF_BIAS 0
#define OFF_AH   1024
#define OFF_AL   (OFF_AH + 128 * PITCH)   // 35840
#define OFF_BH   (OFF_AL + 128 * PITCH)   // 70656
#define OFF_BL   (OFF_BH + 256 * PITCH)   // 140288
#define SM_TOTAL (OFF_BL + 256 * PITCH)   // 209920

// Aggregation tiling
#define AGG_WARPS 16
#define AGG_NPW 8
#define AGG_NODES (AGG_WARPS * AGG_NPW)
#define AGG_BLOCKS ((NV + AGG_NODES - 1) / AGG_NODES)  // 782

// ---------------- scratch (static device globals; no allocs allowed) -------
__device__ float g_h0[(size_t)NV * DD];
__device__ float g_h1[(size_t)NV * DD];
__device__ float g_xb[(size_t)NV * DD];
__device__ int   g_deg[NV];
__device__ int   g_rowptr[NV + 1];
__device__ int   g_cursor[NV];
__device__ int   g_adj[2 * NE];
__device__ float g_dinv[NV];
__device__ float g_part[(size_t)AGG_BLOCKS * 256];
__device__ float g_part2[8 * 256];
__device__ float g_stats[256];
// pre-split weights, dense [n][k] bf16 rows.
// PER LAYER: 256 rows x 128 cols x 2B = 65536 B = 4096 uint4. 3 layers.
#define BCHUNKS_PER_LAYER 4096
__device__ uint4 g_Bh[3 * BCHUNKS_PER_LAYER];
__device__ uint4 g_Bl[3 * BCHUNKS_PER_LAYER];

// ---------------- helpers ----------------------------------------------------
__device__ __forceinline__ uint32_t smem_u32(const void* p) {
    uint32_t a;
    asm("{ .reg .u64 t; cvta.to.shared.u64 t, %1; cvt.u32.u64 %0, t; }" : "=r"(a) : "l"(p));
    return a;
}

__device__ __forceinline__ void ldsm4(uint32_t* r, uint32_t addr) {
    asm volatile("ldmatrix.sync.aligned.m8n8.x4.shared.b16 {%0,%1,%2,%3}, [%4];"
        : "=r"(r[0]), "=r"(r[1]), "=r"(r[2]), "=r"(r[3]) : "r"(addr));
}

__device__ __forceinline__ void mma_bf16(float* d, const uint32_t* a, const uint32_t* b) {
    asm volatile("mma.sync.aligned.m16n8k16.row.col.f32.bf16.bf16.f32 "
        "{%0,%1,%2,%3}, {%4,%5,%6,%7}, {%8,%9}, {%0,%1,%2,%3};"
        : "+f"(d[0]), "+f"(d[1]), "+f"(d[2]), "+f"(d[3])
        : "r"(a[0]), "r"(a[1]), "r"(a[2]), "r"(a[3]), "r"(b[0]), "r"(b[1]));
}

// split (x,y) f32 pair -> packed bf16x2 hi + bf16x2 lo  (lo half of reg = x)
__device__ __forceinline__ void split2(float x, float y, uint32_t& h, uint32_t& l) {
    uint32_t hp;
    asm("cvt.rn.bf16x2.f32 %0, %1, %2;" : "=r"(hp) : "f"(y), "f"(x));
    float xh = __uint_as_float(hp << 16);
    float yh = __uint_as_float(hp & 0xffff0000u);
    float xl = x - xh;
    float yl = y - yh;
    uint32_t lp;
    asm("cvt.rn.bf16x2.f32 %0, %1, %2;" : "=r"(lp) : "f"(yl), "f"(xl));
    h = hp; l = lp;
}

// ---------------- CSR build -------------------------------------------------
__global__ void zero_deg_kernel() {
    int i = blockIdx.x * 256 + threadIdx.x;
    if (i < NV) g_deg[i] = 0;
}

__global__ void deg_kernel(const int2* __restrict__ edges) {
    int e = blockIdx.x * 256 + threadIdx.x;
    if (e >= NE) return;
    int2 ed = edges[e];
    atomicAdd(&g_deg[ed.x], 1);
    atomicAdd(&g_deg[ed.y], 1);
}

__global__ void scan_kernel() {
    __shared__ int sh[1024];
    int t = threadIdx.x;
    const int CH = (NV + 1023) / 1024;
    int base = t * CH;
    int s = 0;
    for (int i = 0; i < CH; i++) {
        int v = base + i;
        if (v < NV) s += g_deg[v];
    }
    sh[t] = s;
    __syncthreads();
    for (int off = 1; off < 1024; off <<= 1) {
        int val = sh[t];
        int add = (t >= off) ? sh[t - off] : 0;
        __syncthreads();
        sh[t] = val + add;
        __syncthreads();
    }
    int run = (t == 0) ? 0 : sh[t - 1];
    for (int i = 0; i < CH; i++) {
        int v = base + i;
        if (v >= NV) break;
        g_rowptr[v] = run;
        g_cursor[v] = run;
        int d = g_deg[v];
        g_dinv[v] = 1.0f / (1.0f + (float)d);
        run += d;
    }
    if (t == 1023) g_rowptr[NV] = run;
}

__global__ void fill_kernel(const int2* __restrict__ edges) {
    int e = blockIdx.x * 256 + threadIdx.x;
    if (e >= NE) return;
    int2 ed = edges[e];
    int p = atomicAdd(&g_cursor[ed.x], 1);
    g_adj[p] = ed.y;
    int q = atomicAdd(&g_cursor[ed.y], 1);
    g_adj[q] = ed.x;
}

// ---------------- weight split prep (all 3 layers) --------------------------
__global__ void prepB_kernel(const float* __restrict__ W0, const float* __restrict__ W1) {
    int idx = blockIdx.x * 256 + threadIdx.x;   // 3*256*128 = 98304
    if (idx >= 3 * TN * DD) return;
    int l = idx / (TN * DD);
    int rem = idx % (TN * DD);
    int n = rem / DD;
    int k = rem % DD;
    float w = (n < DD) ? W0[(size_t)l * DD * DD + n * DD + k]
                       : W1[(size_t)l * DD * DD + (n - DD) * DD + k];
    __nv_bfloat16 hi = __float2bfloat16_rn(w);
    float lof = w - __bfloat162float(hi);
    __nv_bfloat16 lo = __float2bfloat16_rn(lof);
    unsigned short* bh = (unsigned short*)g_Bh;
    unsigned short* bl = (unsigned short*)g_Bl;
    bh[(size_t)l * 32768 + n * DD + k] = __bfloat16_as_ushort(hi);
    bl[(size_t)l * 32768 + n * DD + k] = __bfloat16_as_ushort(lo);
}

// ---------------- mma.sync GEMM: [h0|h1] = X @ [W0^T|W1^T] + [b0|b1] --------
// 512 threads, tile 128x256, warp grid 4m x 4n, warp tile 32x64.
// D = Ahi*Bhi + Ahi*Blo + Alo*Bhi in fp32 accum (3xBF16, rel err ~1e-5).
__global__ void __launch_bounds__(GT, 1)
gemm_kernel(const float* __restrict__ Xext, int use_ext, int layer,
            const float* __restrict__ b0, const float* __restrict__ b1)
{
    const float* X = use_ext ? Xext : g_xb;
    extern __shared__ char smem[];
    uint32_t sb = smem_u32(smem);
    int tid = threadIdx.x;

    // bias -> smem
    float* sbias = (float*)(smem + OFF_BIAS);
    if (tid < 256) sbias[tid] = (tid < DD) ? b0[tid] : b1[tid - DD];

    // B (pre-split bf16) -> padded smem rows: 256 rows x 16 uint4 chunks
    {
        const uint4* srcH = g_Bh + (size_t)layer * BCHUNKS_PER_LAYER;
        const uint4* srcL = g_Bl + (size_t)layer * BCHUNKS_PER_LAYER;
        #pragma unroll
        for (int i = 0; i < 8; i++) {
            int idx = i * GT + tid;       // 4096 16B-chunks per variant
            int n  = idx >> 4;
            int kb = idx & 15;
            uint4 vH = srcH[idx];
            uint4 vL = srcL[idx];
            *(uint4*)(smem + OFF_BH + n * PITCH + kb * 16) = vH;
            *(uint4*)(smem + OFF_BL + n * PITCH + kb * 16) = vL;
        }
    }

    // A: load 128 rows of X, split to bf16 hi/lo, store padded
    int r0 = blockIdx.x * TM;
    {
        int row = tid >> 2;               // 0..127
        int kq  = (tid & 3) * 32;         // quarter of the 128-k row
        int gr  = r0 + row;
        const float4* xv = (const float4*)(X + (size_t)gr * DD + kq);
        #pragma unroll
        for (int j = 0; j < 4; j++) {     // 16B (8 bf16) per iter
            float4 va = (gr < NV) ? xv[2 * j]     : make_float4(0.f, 0.f, 0.f, 0.f);
            float4 vb = (gr < NV) ? xv[2 * j + 1] : make_float4(0.f, 0.f, 0.f, 0.f);
            uint4 h, l;
            split2(va.x, va.y, h.x, l.x);
            split2(va.z, va.w, h.y, l.y);
            split2(vb.x, vb.y, h.z, l.z);
            split2(vb.z, vb.w, h.w, l.w);
            *(uint4*)(smem + OFF_AH + row * PITCH + kq * 2 + j * 16) = h;
            *(uint4*)(smem + OFF_AL + row * PITCH + kq * 2 + j * 16) = l;
        }
    }
    __syncthreads();

    int lane = tid & 31;
    int warp = tid >> 5;
    int wm = warp & 3;        // m group (32 rows)
    int wn = warp >> 2;       // n group (64 cols)

    float acc[2][8][4];
    #pragma unroll
    for (int ms = 0; ms < 2; ms++)
        #pragma unroll
        for (int ns = 0; ns < 8; ns++)
            #pragma unroll
            for (int e = 0; e < 4; e++) acc[ms][ns][e] = 0.f;

    uint32_t a_row_off = (uint32_t)(wm * 32 + (lane & 15)) * PITCH + ((lane >> 4) << 4);
    uint32_t b_row_off = (uint32_t)(wn * 64 + ((lane >> 4) << 3) + (lane & 7)) * PITCH
                       + (((lane >> 3) & 1) << 4);

    #pragma unroll
    for (int ks = 0; ks < 8; ks++) {
        uint32_t ah[2][4], al[2][4];
        #pragma unroll
        for (int ms = 0; ms < 2; ms++) {
            uint32_t addr = sb + OFF_AH + a_row_off + ms * (16 * PITCH) + ks * 32;
            ldsm4(ah[ms], addr);
            ldsm4(al[ms], addr + (OFF_AL - OFF_AH));
        }
        #pragma unroll
        for (int np = 0; np < 4; np++) {
            uint32_t baddr = sb + OFF_BH + b_row_off + np * (16 * PITCH) + ks * 32;
            uint32_t bh[4], bl[4];
            ldsm4(bh, baddr);
            ldsm4(bl, baddr + (OFF_BL - OFF_BH));
            #pragma unroll
            for (int ms = 0; ms < 2; ms++) {
                mma_bf16(acc[ms][2 * np],     ah[ms], bh);
                mma_bf16(acc[ms][2 * np],     ah[ms], bl);
                mma_bf16(acc[ms][2 * np],     al[ms], bh);
                mma_bf16(acc[ms][2 * np + 1], ah[ms], bh + 2);
                mma_bf16(acc[ms][2 * np + 1], ah[ms], bl + 2);
                mma_bf16(acc[ms][2 * np + 1], al[ms], bh + 2);
            }
        }
    }

    // epilogue: bias + route cols 0-127 -> g_h0, 128-255 -> g_h1
    int g  = lane >> 2;
    int i2 = (lane & 3) * 2;
    #pragma unroll
    for (int ms = 0; ms < 2; ms++) {
        #pragma unroll
        for (int ns = 0; ns < 8; ns++) {
            int colg = wn * 64 + ns * 8 + i2;
            float* H = (colg < DD) ? g_h0 : g_h1;
            int c = colg & (DD - 1);
            float bx = sbias[colg], by = sbias[colg + 1];
            int m = r0 + wm * 32 + ms * 16 + g;
            if (m < NV) {
                float2 o = make_float2(acc[ms][ns][0] + bx, acc[ms][ns][1] + by);
                *(float2*)(H + (size_t)m * DD + c) = o;
            }
            if (m + 8 < NV) {
                float2 o = make_float2(acc[ms][ns][2] + bx, acc[ms][ns][3] + by);
                *(float2*)(H + (size_t)(m + 8) * DD + c) = o;
            }
        }
    }
}

// ---------------- aggregate (CSR gather) + dinv scale + BN partial sums ----
__global__ void __launch_bounds__(512)
agg_stats_kernel()
{
    __shared__ float sh[AGG_WARPS * 256];
    int tid  = threadIdx.x;
    int warp = tid >> 5;
    int lane = tid & 31;
    int gw   = blockIdx.x * AGG_WARPS + warp;
    int n0   = gw * AGG_NPW;
    int c4   = lane * 4;

    float4 s = make_float4(0.f, 0.f, 0.f, 0.f);
    float4 q = make_float4(0.f, 0.f, 0.f, 0.f);

    for (int i = 0; i < AGG_NPW; i++) {
        int n = n0 + i;
        if (n >= NV) break;
        float4 acc = *(const float4*)(g_h0 + (size_t)n * DD + c4);
        int beg = g_rowptr[n];
        int end = g_rowptr[n + 1];
        for (int j = beg; j < end; j++) {
            int nb = g_adj[j];
            float4 h = *(const float4*)(g_h1 + (size_t)nb * DD + c4);
            acc.x += h.x; acc.y += h.y; acc.z += h.z; acc.w += h.w;
        }
        float di = g_dinv[n];
        acc.x *= di; acc.y *= di; acc.z *= di; acc.w *= di;
        *(float4*)(g_h0 + (size_t)n * DD + c4) = acc;
        s.x += acc.x; s.y += acc.y; s.z += acc.z; s.w += acc.w;
        q.x += acc.x * acc.x; q.y += acc.y * acc.y;
        q.z += acc.z * acc.z; q.w += acc.w * acc.w;
    }

    float* shw = sh + warp * 256;
    shw[c4 + 0] = s.x; shw[c4 + 1] = s.y; shw[c4 + 2] = s.z; shw[c4 + 3] = s.w;
    shw[128 + c4 + 0] = q.x; shw[128 + c4 + 1] = q.y;
    shw[128 + c4 + 2] = q.z; shw[128 + c4 + 3] = q.w;
    __syncthreads();

    if (tid < 256) {
        float tot = 0.f;
        #pragma unroll
        for (int w = 0; w < AGG_WARPS; w++) tot += sh[w * 256 + tid];
        g_part[(size_t)blockIdx.x * 256 + tid] = tot;
    }
}

__global__ void finalizeA_kernel() {
    int b = blockIdx.x, t = threadIdx.x;
    const int CH = (AGG_BLOCKS + 7) / 8;
    int r0 = b * CH;
    int r1 = r0 + CH; if (r1 > AGG_BLOCKS) r1 = AGG_BLOCKS;
    float s = 0.f;
    for (int r = r0; r < r1; r++) s += g_part[(size_t)r * 256 + t];
    g_part2[b * 256 + t] = s;
}

__global__ void finalizeB_kernel() {
    __shared__ float sh[256];
    int t = threadIdx.x;
    float s = 0.f;
    #pragma unroll
    for (int b = 0; b < 8; b++) s += g_part2[b * 256 + t];
    sh[t] = s;
    __syncthreads();
    if (t < 128) {
        float inv = 1.0f / (float)NV;
        float mu  = sh[t] * inv;
        float var = sh[t + 128] * inv - mu * mu;
        g_stats[t]       = mu;
        g_stats[t + 128] = rsqrtf(var + EPS_BN);
    }
}

// ---------------- BN apply + ReLU (+ residual) ------------------------------
__global__ void __launch_bounds__(256)
bnrelu_kernel(const float* __restrict__ gamma, const float* __restrict__ beta,
              const float* __restrict__ res, float* __restrict__ outExt, int use_ext)
{
    float* out = use_ext ? outExt : g_xb;
    int idx = blockIdx.x * 256 + threadIdx.x;
    if (idx >= NV * 32) return;
    int c = (idx & 31) * 4;

    float4 g = *(const float4*)(g_h0 + (size_t)idx * 4);
    float mu0 = g_stats[c + 0], mu1 = g_stats[c + 1], mu2 = g_stats[c + 2], mu3 = g_stats[c + 3];
    float rs0 = g_stats[128 + c + 0], rs1 = g_stats[128 + c + 1];
    float rs2 = g_stats[128 + c + 2], rs3 = g_stats[128 + c + 3];
    float ga0 = gamma[c + 0], ga1 = gamma[c + 1], ga2 = gamma[c + 2], ga3 = gamma[c + 3];
    float be0 = beta[c + 0], be1 = beta[c + 1], be2 = beta[c + 2], be3 = beta[c + 3];

    float v0 = ga0 * (g.x - mu0) * rs0 + be0;
    float v1 = ga1 * (g.y - mu1) * rs1 + be1;
    float v2 = ga2 * (g.z - mu2) * rs2 + be2;
    float v3 = ga3 * (g.w - mu3) * rs3 + be3;

    if (res != nullptr) {
        float4 r4 = *(const float4*)(res + (size_t)idx * 4);
        v0 += r4.x; v1 += r4.y; v2 += r4.z; v3 += r4.w;
    }
    float4 o = make_float4(fmaxf(v0, 0.f), fmaxf(v1, 0.f), fmaxf(v2, 0.f), fmaxf(v3, 0.f));
    *(float4*)(out + (size_t)idx * 4) = o;
}

// ---------------- launch ----------------------------------------------------
extern "C" void kernel_launch(void* const* d_in, const int* in_sizes, int n_in,
                              void* d_out, int out_size)
{
    const float* features = (const float*)d_in[0];
    const int2*  edges    = (const int2*)d_in[1];
    const float* W0       = (const float*)d_in[2];
    const float* b0       = (const float*)d_in[3];
    const float* W1       = (const float*)d_in[4];
    const float* b1       = (const float*)d_in[5];
    const float* gamma    = (const float*)d_in[6];
    const float* beta     = (const float*)d_in[7];
    float* out = (float*)d_out;

    cudaFuncSetAttribute(gemm_kernel, cudaFuncAttributeMaxDynamicSharedMemorySize, SM_TOTAL);

    // CSR + degree normalization
    zero_deg_kernel<<<(NV + 255) / 256, 256>>>();
    deg_kernel<<<(NE + 255) / 256, 256>>>(edges);
    scan_kernel<<<1, 1024>>>();
    fill_kernel<<<(NE + 255) / 256, 256>>>(edges);

    // pre-split all layer weights
    prepB_kernel<<<(3 * TN * DD + 255) / 256, 256>>>(W0, W1);

    for (int l = 0; l < NL; l++) {
        gemm_kernel<<<NTILES, GT, SM_TOTAL>>>(
            features, (l == 0) ? 1 : 0, l,
            b0 + (size_t)l * DD, b1 + (size_t)l * DD);

        agg_stats_kernel<<<AGG_BLOCKS, 512>>>();
        finalizeA_kernel<<<8, 256>>>();
        finalizeB_kernel<<<1, 256>>>();

        bnrelu_kernel<<<(NV * 32 + 255) / 256, 256>>>(
            gamma + (size_t)l * DD, beta + (size_t)l * DD,
            (l == 2) ? features : nullptr,
            out, (l == 2) ? 1 : 0);
    }
}

// round 8
// speedup vs baseline: 1.5014x; 1.0625x over previous
#include <cuda_runtime.h>
#include <cuda_bf16.h>
#include <cstdint>
#include <cstddef>

// Problem constants (fixed shapes per reference)
#define NV 100000
#define NE 300000
#define DD 128
#define NL 3
#define EPS_BN 1e-5f

// GEMM tiling (mma.sync bf16, 3-term split)
#define TM 128
#define TN 256
#define NTILES ((NV + TM - 1) / TM)  // 782
#define GT 512                        // threads per GEMM block (16 warps)

// smem byte offsets; rows are 128 bf16 = 256B data + 16B pad = 272B pitch
// (272 mod 128 = 16 -> 8 consecutive rows sweep all banks; LDSM conflict-free)
#define PITCH 272
#define OFF_BIAS 0                         // 256 f32 = 1KB
#define OFF_BN   1024                      // 512 f32 = 2KB (gamma|beta|mu|rs)
#define OFF_AH   4096
#define OFF_AL   (OFF_AH + 128 * PITCH)    // 38912
#define OFF_BH   (OFF_AL + 128 * PITCH)    // 73728
#define OFF_BL   (OFF_BH + 256 * PITCH)    // 143360
#define SM_TOTAL (OFF_BL + 256 * PITCH)    // 212992

// Aggregation tiling
#define AGG_WARPS 16
#define AGG_NPW 4
#define AGG_NODES (AGG_WARPS * AGG_NPW)               // 64
#define AGG_BLOCKS ((NV + AGG_NODES - 1) / AGG_NODES) // 1563

// ---------------- scratch (static device globals; no allocs allowed) -------
__device__ float g_h0[(size_t)NV * DD];
__device__ float g_h1[(size_t)NV * DD];
__device__ int   g_deg[NV];
__device__ int   g_rowptr[NV + 1];
__device__ int   g_cursor[NV];
__device__ int   g_adj[2 * NE];
__device__ float g_dinv[NV];
__device__ float g_acc256[256];   // BN partial accumulator (self-zeroing)
__device__ float g_stats[256];    // [0:128) mu, [128:256) rsigma
// pre-split weights, dense [n][k] bf16 rows. 4096 uint4 per layer.
#define BCHUNKS_PER_LAYER 4096
__device__ uint4 g_Bh[3 * BCHUNKS_PER_LAYER];
__device__ uint4 g_Bl[3 * BCHUNKS_PER_LAYER];

// ---------------- helpers ----------------------------------------------------
__device__ __forceinline__ uint32_t smem_u32(const void* p) {
    uint32_t a;
    asm("{ .reg .u64 t; cvta.to.shared.u64 t, %1; cvt.u32.u64 %0, t; }" : "=r"(a) : "l"(p));
    return a;
}

__device__ __forceinline__ void ldsm4(uint32_t* r, uint32_t addr) {
    asm volatile("ldmatrix.sync.aligned.m8n8.x4.shared.b16 {%0,%1,%2,%3}, [%4];"
        : "=r"(r[0]), "=r"(r[1]), "=r"(r[2]), "=r"(r[3]) : "r"(addr));
}

__device__ __forceinline__ void mma_bf16(float* d, const uint32_t* a, const uint32_t* b) {
    asm volatile("mma.sync.aligned.m16n8k16.row.col.f32.bf16.bf16.f32 "
        "{%0,%1,%2,%3}, {%4,%5,%6,%7}, {%8,%9}, {%0,%1,%2,%3};"
        : "+f"(d[0]), "+f"(d[1]), "+f"(d[2]), "+f"(d[3])
        : "r"(a[0]), "r"(a[1]), "r"(a[2]), "r"(a[3]), "r"(b[0]), "r"(b[1]));
}

// split (x,y) f32 pair -> packed bf16x2 hi + bf16x2 lo  (lo half of reg = x)
__device__ __forceinline__ void split2(float x, float y, uint32_t& h, uint32_t& l) {
    uint32_t hp;
    asm("cvt.rn.bf16x2.f32 %0, %1, %2;" : "=r"(hp) : "f"(y), "f"(x));
    float xh = __uint_as_float(hp << 16);
    float yh = __uint_as_float(hp & 0xffff0000u);
    float xl = x - xh;
    float yl = y - yh;
    uint32_t lp;
    asm("cvt.rn.bf16x2.f32 %0, %1, %2;" : "=r"(lp) : "f"(yl), "f"(xl));
    h = hp; l = lp;
}

// ---------------- CSR build -------------------------------------------------
__global__ void zero_deg_kernel() {
    int i = blockIdx.x * 256 + threadIdx.x;
    if (i < NV) g_deg[i] = 0;
}

__global__ void deg_kernel(const int2* __restrict__ edges) {
    int e = blockIdx.x * 256 + threadIdx.x;
    if (e >= NE) return;
    int2 ed = edges[e];
    atomicAdd(&g_deg[ed.x], 1);
    atomicAdd(&g_deg[ed.y], 1);
}

__global__ void scan_kernel() {
    __shared__ int sh[1024];
    int t = threadIdx.x;
    const int CH = (NV + 1023) / 1024;
    int base = t * CH;
    int s = 0;
    for (int i = 0; i < CH; i++) {
        int v = base + i;
        if (v < NV) s += g_deg[v];
    }
    sh[t] = s;
    __syncthreads();
    for (int off = 1; off < 1024; off <<= 1) {
        int val = sh[t];
        int add = (t >= off) ? sh[t - off] : 0;
        __syncthreads();
        sh[t] = val + add;
        __syncthreads();
    }
    int run = (t == 0) ? 0 : sh[t - 1];
    for (int i = 0; i < CH; i++) {
        int v = base + i;
        if (v >= NV) break;
        g_rowptr[v] = run;
        g_cursor[v] = run;
        int d = g_deg[v];
        g_dinv[v] = 1.0f / (1.0f + (float)d);
        run += d;
    }
    if (t == 1023) g_rowptr[NV] = run;
}

__global__ void fill_kernel(const int2* __restrict__ edges) {
    int e = blockIdx.x * 256 + threadIdx.x;
    if (e >= NE) return;
    int2 ed = edges[e];
    int p = atomicAdd(&g_cursor[ed.x], 1);
    g_adj[p] = ed.y;
    int q = atomicAdd(&g_cursor[ed.y], 1);
    g_adj[q] = ed.x;
}

// ---------------- weight split prep (all 3 layers) --------------------------
__global__ void prepB_kernel(const float* __restrict__ W0, const float* __restrict__ W1) {
    int idx = blockIdx.x * 256 + threadIdx.x;   // 3*256*128 = 98304
    if (idx >= 3 * TN * DD) return;
    int l = idx / (TN * DD);
    int rem = idx % (TN * DD);
    int n = rem / DD;
    int k = rem % DD;
    float w = (n < DD) ? W0[(size_t)l * DD * DD + n * DD + k]
                       : W1[(size_t)l * DD * DD + (n - DD) * DD + k];
    __nv_bfloat16 hi = __float2bfloat16_rn(w);
    float lof = w - __bfloat162float(hi);
    __nv_bfloat16 lo = __float2bfloat16_rn(lof);
    unsigned short* bh = (unsigned short*)g_Bh;
    unsigned short* bl = (unsigned short*)g_Bl;
    bh[(size_t)l * 32768 + n * DD + k] = __bfloat16_as_ushort(hi);
    bl[(size_t)l * 32768 + n * DD + k] = __bfloat16_as_ushort(lo);
}

// ---------------- mma.sync GEMM: [h0|h1] = X' @ [W0^T|W1^T] + [b0|b1] ------
// X' = use_bn ? relu(bn(g_h0)) (fused, stats/params in smem) : features.
// 512 threads, tile 128x256, warp grid 4m x 4n, warp tile 32x64.
// D = Ahi*Bhi + Ahi*Blo + Alo*Bhi in fp32 accum (3xBF16, rel err ~1e-5).
__global__ void __launch_bounds__(GT, 1)
gemm_kernel(const float* __restrict__ Xext, int use_bn, int layer,
            const float* __restrict__ b0, const float* __restrict__ b1,
            const float* __restrict__ gamma_prev, const float* __restrict__ beta_prev)
{
    const float* X = use_bn ? g_h0 : Xext;
    extern __shared__ char smem[];
    uint32_t sb = smem_u32(smem);
    int tid = threadIdx.x;

    // bias -> smem
    float* sbias = (float*)(smem + OFF_BIAS);
    if (tid < 256) sbias[tid] = (tid < DD) ? b0[tid] : b1[tid - DD];

    // BN params of PREVIOUS layer -> smem (gamma|beta|mu|rs)
    if (use_bn && tid < 128) {
        float* s_bn = (float*)(smem + OFF_BN);
        s_bn[tid]       = gamma_prev[tid];
        s_bn[128 + tid] = beta_prev[tid];
        s_bn[256 + tid] = g_stats[tid];
        s_bn[384 + tid] = g_stats[128 + tid];
    }
    __syncthreads();

    // B (pre-split bf16) -> padded smem rows: 256 rows x 16 uint4 chunks
    {
        const uint4* srcH = g_Bh + (size_t)layer * BCHUNKS_PER_LAYER;
        const uint4* srcL = g_Bl + (size_t)layer * BCHUNKS_PER_LAYER;
        #pragma unroll
        for (int i = 0; i < 8; i++) {
            int idx = i * GT + tid;       // 4096 16B-chunks per variant
            int n  = idx >> 4;
            int kb = idx & 15;
            uint4 vH = srcH[idx];
            uint4 vL = srcL[idx];
            *(uint4*)(smem + OFF_BH + n * PITCH + kb * 16) = vH;
            *(uint4*)(smem + OFF_BL + n * PITCH + kb * 16) = vL;
        }
    }

    // A: load 128 rows, optional fused BN+ReLU, split bf16 hi/lo, store padded
    int r0 = blockIdx.x * TM;
    {
        int row = tid >> 2;               // 0..127
        int kq  = (tid & 3) * 32;         // quarter of the 128-k row
        int gr  = r0 + row;
        const float4* xv = (const float4*)(X + (size_t)gr * DD + kq);
        const float4* bn4 = (const float4*)(smem + OFF_BN);
        #pragma unroll
        for (int j = 0; j < 4; j++) {     // 16B (8 bf16) per iter
            float4 va = (gr < NV) ? xv[2 * j]     : make_float4(0.f, 0.f, 0.f, 0.f);
            float4 vb = (gr < NV) ? xv[2 * j + 1] : make_float4(0.f, 0.f, 0.f, 0.f);
            if (use_bn) {
                int cA = (kq + j * 8) >> 2;          // float4 index (cols/4)
                float4 gaA = bn4[cA],      gaB = bn4[cA + 1];
                float4 beA = bn4[32 + cA], beB = bn4[32 + cA + 1];
                float4 muA = bn4[64 + cA], muB = bn4[64 + cA + 1];
                float4 rsA = bn4[96 + cA], rsB = bn4[96 + cA + 1];
                va.x = fmaxf(gaA.x * (va.x - muA.x) * rsA.x + beA.x, 0.f);
                va.y = fmaxf(gaA.y * (va.y - muA.y) * rsA.y + beA.y, 0.f);
                va.z = fmaxf(gaA.z * (va.z - muA.z) * rsA.z + beA.z, 0.f);
                va.w = fmaxf(gaA.w * (va.w - muA.w) * rsA.w + beA.w, 0.f);
                vb.x = fmaxf(gaB.x * (vb.x - muB.x) * rsB.x + beB.x, 0.f);
                vb.y = fmaxf(gaB.y * (vb.y - muB.y) * rsB.y + beB.y, 0.f);
                vb.z = fmaxf(gaB.z * (vb.z - muB.z) * rsB.z + beB.z, 0.f);
                vb.w = fmaxf(gaB.w * (vb.w - muB.w) * rsB.w + beB.w, 0.f);
            }
            uint4 h, l;
            split2(va.x, va.y, h.x, l.x);
            split2(va.z, va.w, h.y, l.y);
            split2(vb.x, vb.y, h.z, l.z);
            split2(vb.z, vb.w, h.w, l.w);
            *(uint4*)(smem + OFF_AH + row * PITCH + kq * 2 + j * 16) = h;
            *(uint4*)(smem + OFF_AL + row * PITCH + kq * 2 + j * 16) = l;
        }
    }
    __syncthreads();

    int lane = tid & 31;
    int warp = tid >> 5;
    int wm = warp & 3;        // m group (32 rows)
    int wn = warp >> 2;       // n group (64 cols)

    float acc[2][8][4];
    #pragma unroll
    for (int ms = 0; ms < 2; ms++)
        #pragma unroll
        for (int ns = 0; ns < 8; ns++)
            #pragma unroll
            for (int e = 0; e < 4; e++) acc[ms][ns][e] = 0.f;

    uint32_t a_row_off = (uint32_t)(wm * 32 + (lane & 15)) * PITCH + ((lane >> 4) << 4);
    uint32_t b_row_off = (uint32_t)(wn * 64 + ((lane >> 4) << 3) + (lane & 7)) * PITCH
                       + (((lane >> 3) & 1) << 4);

    #pragma unroll
    for (int ks = 0; ks < 8; ks++) {
        uint32_t ah[2][4], al[2][4];
        #pragma unroll
        for (int ms = 0; ms < 2; ms++) {
            uint32_t addr = sb + OFF_AH + a_row_off + ms * (16 * PITCH) + ks * 32;
            ldsm4(ah[ms], addr);
            ldsm4(al[ms], addr + (OFF_AL - OFF_AH));
        }
        #pragma unroll
        for (int np = 0; np < 4; np++) {
            uint32_t baddr = sb + OFF_BH + b_row_off + np * (16 * PITCH) + ks * 32;
            uint32_t bh[4], bl[4];
            ldsm4(bh, baddr);
            ldsm4(bl, baddr + (OFF_BL - OFF_BH));
            #pragma unroll
            for (int ms = 0; ms < 2; ms++) {
                mma_bf16(acc[ms][2 * np],     ah[ms], bh);
                mma_bf16(acc[ms][2 * np],     ah[ms], bl);
                mma_bf16(acc[ms][2 * np],     al[ms], bh);
                mma_bf16(acc[ms][2 * np + 1], ah[ms], bh + 2);
                mma_bf16(acc[ms][2 * np + 1], ah[ms], bl + 2);
                mma_bf16(acc[ms][2 * np + 1], al[ms], bh + 2);
            }
        }
    }

    // epilogue: bias + route cols 0-127 -> g_h0, 128-255 -> g_h1
    int g  = lane >> 2;
    int i2 = (lane & 3) * 2;
    #pragma unroll
    for (int ms = 0; ms < 2; ms++) {
        #pragma unroll
        for (int ns = 0; ns < 8; ns++) {
            int colg = wn * 64 + ns * 8 + i2;
            float* H = (colg < DD) ? g_h0 : g_h1;
            int c = colg & (DD - 1);
            float bx = sbias[colg], by = sbias[colg + 1];
            int m = r0 + wm * 32 + ms * 16 + g;
            if (m < NV) {
                float2 o = make_float2(acc[ms][ns][0] + bx, acc[ms][ns][1] + by);
                *(float2*)(H + (size_t)m * DD + c) = o;
            }
            if (m + 8 < NV) {
                float2 o = make_float2(acc[ms][ns][2] + bx, acc[ms][ns][3] + by);
                *(float2*)(H + (size_t)(m + 8) * DD + c) = o;
            }
        }
    }
}

// ---------------- aggregate (CSR gather, batched MLP) + BN partial sums ----
// one warp per 4 nodes; lane covers 4 columns. Neighbor loop batched by 4
// so adjacency loads + row gathers issue independently (MLP ~4-8).
__global__ void __launch_bounds__(512)
agg_stats_kernel()
{
    __shared__ float sh[AGG_WARPS * 256];
    int tid  = threadIdx.x;
    int warp = tid >> 5;
    int lane = tid & 31;
    int gw   = blockIdx.x * AGG_WARPS + warp;
    int n0   = gw * AGG_NPW;
    int c4   = lane * 4;

    float4 s = make_float4(0.f, 0.f, 0.f, 0.f);
    float4 q = make_float4(0.f, 0.f, 0.f, 0.f);

    #pragma unroll
    for (int i = 0; i < AGG_NPW; i++) {
        int n = n0 + i;
        if (n >= NV) break;
        float4 acc = *(const float4*)(g_h0 + (size_t)n * DD + c4);
        int beg = g_rowptr[n];
        int end = g_rowptr[n + 1];
        int j = beg;
        for (; j + 4 <= end; j += 4) {
            int a0 = g_adj[j], a1 = g_adj[j + 1], a2 = g_adj[j + 2], a3 = g_adj[j + 3];
            float4 v0 = *(const float4*)(g_h1 + (size_t)a0 * DD + c4);
            float4 v1 = *(const float4*)(g_h1 + (size_t)a1 * DD + c4);
            float4 v2 = *(const float4*)(g_h1 + (size_t)a2 * DD + c4);
            float4 v3 = *(const float4*)(g_h1 + (size_t)a3 * DD + c4);
            acc.x += (v0.x + v1.x) + (v2.x + v3.x);
            acc.y += (v0.y + v1.y) + (v2.y + v3.y);
            acc.z += (v0.z + v1.z) + (v2.z + v3.z);
            acc.w += (v0.w + v1.w) + (v2.w + v3.w);
        }
        for (; j < end; j++) {
            int a = g_adj[j];
            float4 v = *(const float4*)(g_h1 + (size_t)a * DD + c4);
            acc.x += v.x; acc.y += v.y; acc.z += v.z; acc.w += v.w;
        }
        float di = g_dinv[n];
        acc.x *= di; acc.y *= di; acc.z *= di; acc.w *= di;
        *(float4*)(g_h0 + (size_t)n * DD + c4) = acc;
        s.x += acc.x; s.y += acc.y; s.z += acc.z; s.w += acc.w;
        q.x += acc.x * acc.x; q.y += acc.y * acc.y;
        q.z += acc.z * acc.z; q.w += acc.w * acc.w;
    }

    float* shw = sh + warp * 256;
    shw[c4 + 0] = s.x; shw[c4 + 1] = s.y; shw[c4 + 2] = s.z; shw[c4 + 3] = s.w;
    shw[128 + c4 + 0] = q.x; shw[128 + c4 + 1] = q.y;
    shw[128 + c4 + 2] = q.z; shw[128 + c4 + 3] = q.w;
    __syncthreads();

    if (tid < 256) {
        float tot = 0.f;
        #pragma unroll
        for (int w = 0; w < AGG_WARPS; w++) tot += sh[w * 256 + tid];
        atomicAdd(&g_acc256[tid], tot);
    }
}

// single block: finish BN stats, then re-zero the accumulator for next use
__global__ void finalize_kernel() {
    int t = threadIdx.x;
    if (t < 128) {
        float su = g_acc256[t];
        float sq = g_acc256[t + 128];
        float inv = 1.0f / (float)NV;
        float mu  = su * inv;
        float var = sq * inv - mu * mu;
        g_stats[t]       = mu;
        g_stats[t + 128] = rsqrtf(var + EPS_BN);
    }
    __syncthreads();
    g_acc256[t] = 0.f;
}

// ---------------- final BN apply + residual + ReLU -> d_out -----------------
__global__ void __launch_bounds__(256)
bnrelu_kernel(const float* __restrict__ gamma, const float* __restrict__ beta,
              const float* __restrict__ res, float* __restrict__ out)
{
    int idx = blockIdx.x * 256 + threadIdx.x;
    if (idx >= NV * 32) return;
    int c = (idx & 31) * 4;

    float4 g = *(const float4*)(g_h0 + (size_t)idx * 4);
    float mu0 = g_stats[c + 0], mu1 = g_stats[c + 1], mu2 = g_stats[c + 2], mu3 = g_stats[c + 3];
    float rs0 = g_stats[128 + c + 0], rs1 = g_stats[128 + c + 1];
    float rs2 = g_stats[128 + c + 2], rs3 = g_stats[128 + c + 3];
    float ga0 = gamma[c + 0], ga1 = gamma[c + 1], ga2 = gamma[c + 2], ga3 = gamma[c + 3];
    float be0 = beta[c + 0], be1 = beta[c + 1], be2 = beta[c + 2], be3 = beta[c + 3];

    float4 r4 = *(const float4*)(res + (size_t)idx * 4);
    float v0 = ga0 * (g.x - mu0) * rs0 + be0 + r4.x;
    float v1 = ga1 * (g.y - mu1) * rs1 + be1 + r4.y;
    float v2 = ga2 * (g.z - mu2) * rs2 + be2 + r4.z;
    float v3 = ga3 * (g.w - mu3) * rs3 + be3 + r4.w;

    float4 o = make_float4(fmaxf(v0, 0.f), fmaxf(v1, 0.f), fmaxf(v2, 0.f), fmaxf(v3, 0.f));
    *(float4*)(out + (size_t)idx * 4) = o;
}

// ---------------- launch ----------------------------------------------------
extern "C" void kernel_launch(void* const* d_in, const int* in_sizes, int n_in,
                              void* d_out, int out_size)
{
    const float* features = (const float*)d_in[0];
    const int2*  edges    = (const int2*)d_in[1];
    const float* W0       = (const float*)d_in[2];
    const float* b0       = (const float*)d_in[3];
    const float* W1       = (const float*)d_in[4];
    const float* b1       = (const float*)d_in[5];
    const float* gamma    = (const float*)d_in[6];
    const float* beta     = (const float*)d_in[7];
    float* out = (float*)d_out;

    cudaFuncSetAttribute(gemm_kernel, cudaFuncAttributeMaxDynamicSharedMemorySize, SM_TOTAL);

    // CSR + degree normalization
    zero_deg_kernel<<<(NV + 255) / 256, 256>>>();
    deg_kernel<<<(NE + 255) / 256, 256>>>(edges);
    scan_kernel<<<1, 1024>>>();
    fill_kernel<<<(NE + 255) / 256, 256>>>(edges);

    // pre-split all layer weights
    prepB_kernel<<<(3 * TN * DD + 255) / 256, 256>>>(W0, W1);

    for (int l = 0; l < NL; l++) {
        // layer l GEMM; for l>0, BN+ReLU of layer l-1 fused into A-load
        gemm_kernel<<<NTILES, GT, SM_TOTAL>>>(
            features, (l == 0) ? 0 : 1, l,
            b0 + (size_t)l * DD, b1 + (size_t)l * DD,
            gamma + (size_t)(l > 0 ? l - 1 : 0) * DD,
            beta  + (size_t)(l > 0 ? l - 1 : 0) * DD);

        agg_stats_kernel<<<AGG_BLOCKS, 512>>>();
        finalize_kernel<<<1, 256>>>();
    }

    // final BN + residual + ReLU -> d_out
    bnrelu_kernel<<<(NV * 32 + 255) / 256, 256>>>(
        gamma + (size_t)2 * DD, beta + (size_t)2 * DD, features, out);
}